// round 12
// baseline (speedup 1.0000x reference)
#include <cuda_runtime.h>
#include <cstdint>

#define N_NODES 128
#define V_PTS   2048
#define XYZ     63
#define NG      9          // node groups: 8 groups of 15 + 1 group of 8

// ---- output layout ----
#define OFF_C      0
#define OFF_D      6144
#define OFF_EI     8192
#define OFF_DELTA  12288
#define OFF_MEAN   12672
#define OFF_LOGVAR 13696

// ---- scratch ----
__device__ float g_ei[N_NODES * 32];
__device__ float g_b1eff[N_NODES * 64];
__device__ float g_e[N_NODES * V_PTS];
__device__ float g_fblend[V_PTS * 256];          // 2MB blended features (atomic-accumulated)
// per-node packed weight image: tf32-rounded, K-interleaved, stride-72 rows
__device__ float4 g_Wpad4[N_NODES * 8064];

// ---- field smem layout (float offsets) ----
#define F_BUFA 0        // 128 x 72 activation buffer (K-interleaved)
#define F_BUFB 9216
#define F_W1   18432    // 64 x 72
#define F_W2   23040
#define F_W3   27648
#define F_W4   32256    // 256 x 72
#define F_B1   50688
#define F_B2   50752
#define F_B3   50816
#define F_B4   50880
#define F_E    51136
#define F_TOT  51264    // 205056 bytes

// pair-scoped named barrier: the two warps sharing mb (64 threads)
#define PAIRB(mbid) asm volatile("bar.sync %0, 64;" :: "r"((mbid) + 1) : "memory")

// K-interleave within each 8-column group: pairs (k, k+4) adjacent.
__device__ __forceinline__ int invk(int s) {    // original col stored at position s
    return (s & ~7) | (((s & 1) << 2) | ((s & 6) >> 1));
}

__device__ __forceinline__ float to_tf32(float x) {
    uint32_t r;
    asm("cvt.rna.tf32.f32 %0, %1;" : "=r"(r) : "f"(x));
    return __uint_as_float(r);
}

__device__ __forceinline__ void mma_tf32(float c[4], uint32_t a0, uint32_t a1,
                                         uint32_t a2, uint32_t a3,
                                         uint32_t b0, uint32_t b1) {
    asm volatile(
        "mma.sync.aligned.m16n8k8.row.col.f32.tf32.tf32.f32 "
        "{%0,%1,%2,%3}, {%4,%5,%6,%7}, {%8,%9}, {%0,%1,%2,%3};"
        : "+f"(c[0]), "+f"(c[1]), "+f"(c[2]), "+f"(c[3])
        : "r"(a0), "r"(a1), "r"(a2), "r"(a3), "r"(b0), "r"(b1));
}

// one warp computes a 16x32 tile of C[128 x N] = A[128 x 64] * W[N x 64]^T
// K-interleaved layout: fragment pairs (k, k+4) adjacent -> LDS.64 loads.
__device__ __forceinline__ void gemm16x32(const float* __restrict__ Ain,
                                          const float* __restrict__ Ws,
                                          int mb, int cb, int lane,
                                          float c[4][4]) {
    int r   = mb * 16 + (lane >> 2);
    int kk2 = (lane & 3) * 2;
    const float* ar0 = Ain + r * 72 + kk2;
    const float* ar1 = ar0 + 8 * 72;
    const float* bc  = Ws + (cb + (lane >> 2)) * 72 + kk2;
    #pragma unroll
    for (int k8 = 0; k8 < 8; k8++) {
        float2 a0 = *(const float2*)&ar0[k8 * 8];
        float2 a1 = *(const float2*)&ar1[k8 * 8];
        #pragma unroll
        for (int n8 = 0; n8 < 4; n8++) {
            float2 b = *(const float2*)&bc[n8 * 8 * 72 + k8 * 8];
            mma_tf32(c[n8],
                     __float_as_uint(a0.x), __float_as_uint(a1.x),
                     __float_as_uint(a0.y), __float_as_uint(a1.y),
                     __float_as_uint(b.x),  __float_as_uint(b.y));
        }
    }
}

// =====================================================================
// Kernel A: encoder + decoder + effective L1 bias (fp32 exact)
// =====================================================================
__global__ void setup_kernel(
    const float* __restrict__ poses, const float* __restrict__ t_ped,
    const float* __restrict__ w,
    const float* __restrict__ Wec1, const float* __restrict__ bec1,
    const float* __restrict__ Wec21, const float* __restrict__ bec21,
    const float* __restrict__ Wec22, const float* __restrict__ bec22,
    const float* __restrict__ Wdc1, const float* __restrict__ bdc1,
    const float* __restrict__ Wdc21, const float* __restrict__ bdc21,
    const float* __restrict__ Wdc22, const float* __restrict__ bdc22,
    const float* __restrict__ Wf1, const float* __restrict__ bf1,
    float* __restrict__ out)
{
    int n = blockIdx.x;
    int t = threadIdx.x;
    __shared__ float s_in[88], s_net[64], s_mean[8], s_din[80], s_net2[64], s_ei[32];

    if (t < 72)       s_in[t] = w[n * 24 + t / 3] * poses[n * 72 + t];
    else if (t < 88)  s_in[t] = t_ped[t - 72];
    __syncthreads();

    if (t < 64) {
        float a = bec1[n * 64 + t];
        const float* Wr = &Wec1[(n * 64 + t) * 88];
        #pragma unroll 8
        for (int c = 0; c < 88; c++) a += Wr[c] * s_in[c];
        s_net[t] = fmaxf(a, 0.f);
    }
    __syncthreads();

    if (t < 8) {
        float m = bec21[n * 8 + t], lv = bec22[n * 8 + t];
        const float* Wm = &Wec21[(n * 8 + t) * 64];
        const float* Wl = &Wec22[(n * 8 + t) * 64];
        #pragma unroll 8
        for (int c = 0; c < 64; c++) { m += Wm[c] * s_net[c]; lv += Wl[c] * s_net[c]; }
        s_mean[t] = m;
        out[OFF_MEAN + n * 8 + t] = m;
        out[OFF_LOGVAR + n * 8 + t] = lv;
    }
    __syncthreads();

    if (t < 72)      s_din[t] = s_in[t];
    else if (t < 80) s_din[t] = s_mean[t - 72];
    __syncthreads();

    if (t < 64) {
        float a = bdc1[n * 64 + t];
        const float* Wr = &Wdc1[(n * 64 + t) * 80];
        #pragma unroll 8
        for (int c = 0; c < 80; c++) a += Wr[c] * s_din[c];
        s_net2[t] = fmaxf(a, 0.f);
    }
    __syncthreads();

    if (t < 32) {
        float a = bdc21[n * 32 + t];
        const float* Wr = &Wdc21[(n * 32 + t) * 64];
        #pragma unroll 8
        for (int c = 0; c < 64; c++) a += Wr[c] * s_net2[c];
        s_ei[t] = a;
        g_ei[n * 32 + t] = a;
        out[OFF_EI + n * 32 + t] = a;
    }
    if (t >= 32 && t < 35) {
        int j = t - 32;
        float a = bdc22[n * 3 + j];
        const float* Wr = &Wdc22[(n * 3 + j) * 64];
        #pragma unroll 8
        for (int c = 0; c < 64; c++) a += Wr[c] * s_net2[c];
        out[OFF_DELTA + n * 3 + j] = a;
    }
    __syncthreads();

    if (t < 64) {
        float a = bf1[n * 64 + t];
        const float* Wr = &Wf1[(size_t)(n * 64 + t) * 95];
        #pragma unroll 8
        for (int c = 0; c < 32; c++) a += Wr[c] * s_ei[c];
        g_b1eff[n * 64 + t] = a;
    }
}

// =====================================================================
// Kernel B: RBF blend weights, normalized (fp32 exact)
// =====================================================================
__global__ void bweight_kernel(const float* __restrict__ wpts,
                               const float* __restrict__ nodes_posed)
{
    int v = blockIdx.x * blockDim.x + threadIdx.x;
    if (v >= V_PTS) return;
    float px = wpts[v * 3 + 0], py = wpts[v * 3 + 1], pz = wpts[v * 3 + 2];
    float denom = 0.f;
    for (int n = 0; n < N_NODES; n++) {
        float dx = px - nodes_posed[n * 3 + 0];
        float dy = py - nodes_posed[n * 3 + 1];
        float dz = pz - nodes_posed[n * 3 + 2];
        float d2 = dx * dx + dy * dy + dz * dz;
        float influ = expf(-d2 * (1.0f / 0.18f)) - 0.01f;
        float e = (influ >= 0.f) ? (influ + 1e-7f) : 0.f;
        denom += fmaxf(influ, 0.f) + 1e-7f;
        g_e[n * V_PTS + v] = e;
    }
    float inv = 1.0f / denom;
    for (int n = 0; n < N_NODES; n++) g_e[n * V_PTS + v] *= inv;
}

// =====================================================================
// Kernel Z: zero the blend accumulator
// =====================================================================
__global__ void zero_kernel()
{
    int i = blockIdx.x * blockDim.x + threadIdx.x;
    g_fblend[i] = 0.f;
}

// =====================================================================
// Kernel E: prepack weights -> tf32, K-interleaved, stride-72 rows
// =====================================================================
__global__ void prepack_kernel(const float* __restrict__ Wf1,
                               const float* __restrict__ Wf2,
                               const float* __restrict__ Wf3,
                               const float* __restrict__ Wf4)
{
    int n = blockIdx.x, tid = threadIdx.x;   // 256 threads
    float* dst = (float*)&g_Wpad4[(size_t)n * 8064];

    for (int i = tid; i < 4608; i += 256) {            // W1 [64 x 72]
        int j = i / 72, s = i - j * 72;
        float v = 0.f;
        if (s < 64) { int k = invk(s); if (k < XYZ) v = Wf1[(size_t)(n * 64 + j) * 95 + 32 + k]; }
        dst[i] = to_tf32(v);
    }
    for (int i = tid; i < 4608; i += 256) {            // W2
        int j = i / 72, s = i - j * 72;
        float v = 0.f;
        if (s < 64) v = Wf2[(size_t)n * 4096 + j * 64 + invk(s)];
        dst[4608 + i] = to_tf32(v);
    }
    for (int i = tid; i < 4608; i += 256) {            // W3
        int j = i / 72, s = i - j * 72;
        float v = 0.f;
        if (s < 64) v = Wf3[(size_t)n * 4096 + j * 64 + invk(s)];
        dst[9216 + i] = to_tf32(v);
    }
    for (int i = tid; i < 18432; i += 256) {           // W4 [256 x 72]
        int j = i / 72, s = i - j * 72;
        float v = 0.f;
        if (s < 64) v = Wf4[(size_t)n * 16384 + j * 64 + invk(s)];
        dst[13824 + i] = to_tf32(v);
    }
}

// =====================================================================
// Kernel C: feature field via mma.sync tf32 (HMMA)
// grid = (16 v-tiles) x (9 node-groups), 512 threads (16 warps)
// Inter-layer sync is PAIR-scoped (named barrier per mb, 64 threads).
// =====================================================================
__global__ void __launch_bounds__(512, 1) field_kernel(
    const float* __restrict__ local_coords,
    const float* __restrict__ bf2, const float* __restrict__ bf3,
    const float* __restrict__ bf4)
{
    extern __shared__ float sm[];
    int tid  = threadIdx.x;
    int wid  = tid >> 5, lane = tid & 31;
    int mb   = wid & 7;            // M-block (16 rows)
    int nhi  = wid >> 3;           // 0/1: which 32-col block within 64
    int v0 = blockIdx.x * 128;
    int g  = blockIdx.y;
    int n0 = g * 15;
    int ncnt = (g == 8) ? 8 : 15;
    int cb = nhi * 32;

    // hoisted per-thread constants
    int q2 = (lane & 3) * 2;
    const int peLut[4] = {0, 4, 1, 5};
    int pe = peLut[lane & 3];               // storage pos of even col q2 within 8-group
    int r0 = mb * 16 + (lane >> 2);
    int rowA0 = r0 * 72, rowA1 = (r0 + 8) * 72;
    int scol  = tid & 63;                   // storage col this thread stages
    int kcol  = invk(scol);                 // original lc column (loop-invariant)
    int vbase = tid >> 6;                   // 0..7

    float acc[64];
    #pragma unroll
    for (int i = 0; i < 64; i++) acc[i] = 0.f;

    for (int ni = 0; ni < ncnt; ni++) {
        int n = n0 + ni;
        __syncthreads();   // all reads of previous node done before overwrite

        // ---- stage weights (raw float4 copy of prepacked image) ----
        {
            const float4* src = &g_Wpad4[(size_t)n * 8064];
            float4* dst = ((float4*)sm) + (F_W1 / 4);
            #pragma unroll 4
            for (int i = tid; i < 8064; i += 512) dst[i] = src[i];
        }
        if (tid < 64) {
            sm[F_B1 + tid] = g_b1eff[n * 64 + tid];
            sm[F_B2 + tid] = bf2[n * 64 + tid];
            sm[F_B3 + tid] = bf3[n * 64 + tid];
        }
        if (tid < 256) sm[F_B4 + tid] = bf4[n * 256 + tid];
        if (tid < 128) sm[F_E + tid]  = g_e[(size_t)n * V_PTS + v0 + tid];
        // ---- stage A0 = lc tile [128 x 64] tf32, K-interleaved ----
        {
            const float* lcp = local_coords
                + ((size_t)n * V_PTS + v0 + vbase) * XYZ + kcol;
            #pragma unroll
            for (int j = 0; j < 16; j++) {
                float val = (kcol < XYZ) ? lcp[(size_t)j * 8 * XYZ] : 0.f;
                sm[F_BUFA + (vbase + j * 8) * 72 + scol] = to_tf32(val);
            }
        }
        __syncthreads();

        float ev0 = sm[F_E + r0];
        float ev1 = sm[F_E + r0 + 8];

        // ================= L1: bufA -> bufB =================
        {
            float c[4][4];
            #pragma unroll
            for (int a = 0; a < 4; a++)
                #pragma unroll
                for (int b = 0; b < 4; b++) c[a][b] = 0.f;
            gemm16x32(sm + F_BUFA, sm + F_W1, mb, cb, lane, c);
            #pragma unroll
            for (int n8 = 0; n8 < 4; n8++) {
                int gb = cb + n8 * 8;
                float b0 = sm[F_B1 + gb + q2], b1 = sm[F_B1 + gb + q2 + 1];
                int p0 = gb + pe;
                sm[F_BUFB + rowA0 + p0]     = to_tf32(fmaxf(c[n8][0] + b0, 0.f));
                sm[F_BUFB + rowA0 + p0 + 2] = to_tf32(fmaxf(c[n8][1] + b1, 0.f));
                sm[F_BUFB + rowA1 + p0]     = to_tf32(fmaxf(c[n8][2] + b0, 0.f));
                sm[F_BUFB + rowA1 + p0 + 2] = to_tf32(fmaxf(c[n8][3] + b1, 0.f));
            }
        }
        PAIRB(mb);

        // ================= L2: bufB -> bufA =================
        {
            float c[4][4];
            #pragma unroll
            for (int a = 0; a < 4; a++)
                #pragma unroll
                for (int b = 0; b < 4; b++) c[a][b] = 0.f;
            gemm16x32(sm + F_BUFB, sm + F_W2, mb, cb, lane, c);
            #pragma unroll
            for (int n8 = 0; n8 < 4; n8++) {
                int gb = cb + n8 * 8;
                float b0 = sm[F_B2 + gb + q2], b1 = sm[F_B2 + gb + q2 + 1];
                int p0 = gb + pe;
                sm[F_BUFA + rowA0 + p0]     = to_tf32(fmaxf(c[n8][0] + b0, 0.f));
                sm[F_BUFA + rowA0 + p0 + 2] = to_tf32(fmaxf(c[n8][1] + b1, 0.f));
                sm[F_BUFA + rowA1 + p0]     = to_tf32(fmaxf(c[n8][2] + b0, 0.f));
                sm[F_BUFA + rowA1 + p0 + 2] = to_tf32(fmaxf(c[n8][3] + b1, 0.f));
            }
        }
        PAIRB(mb);

        // ================= L3: bufA -> bufB =================
        {
            float c[4][4];
            #pragma unroll
            for (int a = 0; a < 4; a++)
                #pragma unroll
                for (int b = 0; b < 4; b++) c[a][b] = 0.f;
            gemm16x32(sm + F_BUFA, sm + F_W3, mb, cb, lane, c);
            #pragma unroll
            for (int n8 = 0; n8 < 4; n8++) {
                int gb = cb + n8 * 8;
                float b0 = sm[F_B3 + gb + q2], b1 = sm[F_B3 + gb + q2 + 1];
                int p0 = gb + pe;
                sm[F_BUFB + rowA0 + p0]     = to_tf32(fmaxf(c[n8][0] + b0, 0.f));
                sm[F_BUFB + rowA0 + p0 + 2] = to_tf32(fmaxf(c[n8][1] + b1, 0.f));
                sm[F_BUFB + rowA1 + p0]     = to_tf32(fmaxf(c[n8][2] + b0, 0.f));
                sm[F_BUFB + rowA1 + p0 + 2] = to_tf32(fmaxf(c[n8][3] + b1, 0.f));
            }
        }
        PAIRB(mb);

        // ================= L4: bufB x W4 (256 cols, 4 rounds) =================
        #pragma unroll
        for (int rnd = 0; rnd < 4; rnd++) {
            float c[4][4];
            #pragma unroll
            for (int a = 0; a < 4; a++)
                #pragma unroll
                for (int b = 0; b < 4; b++) c[a][b] = 0.f;
            int cb4 = rnd * 64 + cb;
            gemm16x32(sm + F_BUFB, sm + F_W4, mb, cb4, lane, c);
            #pragma unroll
            for (int n8 = 0; n8 < 4; n8++) {
                int cc = cb4 + n8 * 8 + q2;
                float b0 = sm[F_B4 + cc], b1 = sm[F_B4 + cc + 1];
                int ai = rnd * 16 + n8 * 4;
                acc[ai + 0] += ev0 * fmaxf(c[n8][0] + b0, 0.f);
                acc[ai + 1] += ev0 * fmaxf(c[n8][1] + b1, 0.f);
                acc[ai + 2] += ev1 * fmaxf(c[n8][2] + b0, 0.f);
                acc[ai + 3] += ev1 * fmaxf(c[n8][3] + b1, 0.f);
            }
        }
        // loop-top __syncthreads() covers L4-read completion before restage
    }

    // ---- accumulate into global blend buffer (REDG, spread addresses) ----
    {
        float* fb0 = g_fblend + (size_t)(v0 + r0) * 256;
        float* fb1 = g_fblend + (size_t)(v0 + r0 + 8) * 256;
        #pragma unroll
        for (int rnd = 0; rnd < 4; rnd++) {
            #pragma unroll
            for (int n8 = 0; n8 < 4; n8++) {
                int cc = rnd * 64 + cb + n8 * 8 + q2;
                int ai = rnd * 16 + n8 * 4;
                atomicAdd(&fb0[cc],     acc[ai + 0]);
                atomicAdd(&fb0[cc + 1], acc[ai + 1]);
                atomicAdd(&fb1[cc],     acc[ai + 2]);
                atomicAdd(&fb1[cc + 1], acc[ai + 3]);
            }
        }
    }
}

// =====================================================================
// Kernel D: NeRF head (reads 2MB blended features)
// =====================================================================
__global__ void head_kernel(const float* __restrict__ Wc1, const float* __restrict__ bc1,
                            const float* __restrict__ Wc2, const float* __restrict__ bc2,
                            const float* __restrict__ Wd1, const float* __restrict__ bd1,
                            float* __restrict__ out)
{
    int v = blockIdx.x;
    int t = threadIdx.x;   // 64 threads
    __shared__ float f_s[256];
    __shared__ float netc_s[64];

    *(float4*)&f_s[t * 4] = *(const float4*)&g_fblend[(size_t)v * 256 + t * 4];
    __syncthreads();

    {
        float a0 = 0.f, a1 = 0.f, a2 = 0.f, a3 = 0.f;
        #pragma unroll 8
        for (int c = 0; c < 256; c += 4) {
            a0 += f_s[c + 0] * Wc1[(c + 0) * 64 + t];
            a1 += f_s[c + 1] * Wc1[(c + 1) * 64 + t];
            a2 += f_s[c + 2] * Wc1[(c + 2) * 64 + t];
            a3 += f_s[c + 3] * Wc1[(c + 3) * 64 + t];
        }
        netc_s[t] = fmaxf(bc1[t] + ((a0 + a1) + (a2 + a3)), 0.f);
    }
    __syncthreads();

    if (t < 3) {
        float r = bc2[t];
        #pragma unroll 8
        for (int j = 0; j < 64; j++) r += netc_s[j] * Wc2[j * 3 + t];
        out[OFF_C + v * 3 + t] = r;
    } else if (t == 3) {
        float r0 = 0.f, r1 = 0.f, r2 = 0.f, r3 = 0.f;
        #pragma unroll 8
        for (int c = 0; c < 256; c += 4) {
            r0 += f_s[c + 0] * Wd1[c + 0];
            r1 += f_s[c + 1] * Wd1[c + 1];
            r2 += f_s[c + 2] * Wd1[c + 2];
            r3 += f_s[c + 3] * Wd1[c + 3];
        }
        out[OFF_D + v] = fmaxf(bd1[0] + ((r0 + r1) + (r2 + r3)), 0.f);
    }
}

// =====================================================================
extern "C" void kernel_launch(void* const* d_in, const int* in_sizes, int n_in,
                              void* d_out, int out_size)
{
    const float* poses = (const float*)d_in[0];
    const float* t_ped = (const float*)d_in[1];
    const float* w     = (const float*)d_in[2];
    const float* wpts  = (const float*)d_in[3];
    const float* nodes = (const float*)d_in[4];
    const float* lc    = (const float*)d_in[5];
    const float *Wec1 = (const float*)d_in[6],  *bec1 = (const float*)d_in[7];
    const float *Wec21= (const float*)d_in[8],  *bec21= (const float*)d_in[9];
    const float *Wec22= (const float*)d_in[10], *bec22= (const float*)d_in[11];
    const float *Wdc1 = (const float*)d_in[12], *bdc1 = (const float*)d_in[13];
    const float *Wdc21= (const float*)d_in[14], *bdc21= (const float*)d_in[15];
    const float *Wdc22= (const float*)d_in[16], *bdc22= (const float*)d_in[17];
    const float *Wf1  = (const float*)d_in[18], *bf1  = (const float*)d_in[19];
    const float *Wf2  = (const float*)d_in[20], *bf2  = (const float*)d_in[21];
    const float *Wf3  = (const float*)d_in[22], *bf3  = (const float*)d_in[23];
    const float *Wf4  = (const float*)d_in[24], *bf4  = (const float*)d_in[25];
    const float *Wc1  = (const float*)d_in[26], *bc1  = (const float*)d_in[27];
    const float *Wc2  = (const float*)d_in[28], *bc2  = (const float*)d_in[29];
    const float *Wd1  = (const float*)d_in[30], *bd1  = (const float*)d_in[31];
    float* out = (float*)d_out;

    setup_kernel<<<N_NODES, 128>>>(poses, t_ped, w,
                                   Wec1, bec1, Wec21, bec21, Wec22, bec22,
                                   Wdc1, bdc1, Wdc21, bdc21, Wdc22, bdc22,
                                   Wf1, bf1, out);
    bweight_kernel<<<V_PTS / 256, 256>>>(wpts, nodes);
    prepack_kernel<<<N_NODES, 256>>>(Wf1, Wf2, Wf3, Wf4);
    zero_kernel<<<(V_PTS * 256) / 512, 512>>>();

    cudaFuncSetAttribute(field_kernel,
                         cudaFuncAttributeMaxDynamicSharedMemorySize,
                         F_TOT * (int)sizeof(float));
    field_kernel<<<dim3(V_PTS / 128, NG), 512, F_TOT * sizeof(float)>>>(lc, bf2, bf3, bf4);

    head_kernel<<<V_PTS, 64>>>(Wc1, bc1, Wc2, bc2, Wd1, bd1, out);
}

// round 13
// speedup vs baseline: 1.2131x; 1.2131x over previous
#include <cuda_runtime.h>
#include <cstdint>

#define N_NODES 128
#define V_PTS   2048
#define XYZ     63
#define NG      9          // node groups: 8 groups of 15 + 1 group of 8

// ---- output layout ----
#define OFF_C      0
#define OFF_D      6144
#define OFF_EI     8192
#define OFF_DELTA  12288
#define OFF_MEAN   12672
#define OFF_LOGVAR 13696

// ---- scratch ----
__device__ float g_ei[N_NODES * 32];
__device__ float g_b1eff[N_NODES * 64];
__device__ float g_e[N_NODES * V_PTS];
__device__ float g_fpart[NG * V_PTS * 256];
// per-node packed weight image: tf32-rounded, stride-68 padded rows
// W1 [64x68]=4352 | W2 4352 | W3 4352 | W4 [256x68]=17408  => 30464 floats = 7616 float4
__device__ float4 g_Wpad4[N_NODES * 7616];

// ---- field smem layout (float offsets) ----
#define F_BUFA 0        // 128 x 68 activation buffer
#define F_BUFB 8704
#define F_W1   17408    // 64 x 68
#define F_W2   21760
#define F_W3   26112
#define F_W4   30464    // 256 x 68
#define F_B1   47872
#define F_B2   47936
#define F_B3   48000
#define F_B4   48064
#define F_E    48320
#define F_TOT  48448    // 193792 bytes

__device__ __forceinline__ float to_tf32(float x) {
    uint32_t r;
    asm("cvt.rna.tf32.f32 %0, %1;" : "=r"(r) : "f"(x));
    return __uint_as_float(r);
}

__device__ __forceinline__ void mma_tf32(float c[4], uint32_t a0, uint32_t a1,
                                         uint32_t a2, uint32_t a3,
                                         uint32_t b0, uint32_t b1) {
    asm volatile(
        "mma.sync.aligned.m16n8k8.row.col.f32.tf32.tf32.f32 "
        "{%0,%1,%2,%3}, {%4,%5,%6,%7}, {%8,%9}, {%0,%1,%2,%3};"
        : "+f"(c[0]), "+f"(c[1]), "+f"(c[2]), "+f"(c[3])
        : "r"(a0), "r"(a1), "r"(a2), "r"(a3), "r"(b0), "r"(b1));
}

// one warp computes a 16x16 tile of C[128 x N] = A[128 x 64] * W[N x 64]^T
// c[n8][4] accumulators (n8 = 0,1); rows mb*16 + (lane>>2) and +8;
// cols cb + n8*8 + (lane&3)*2 + {0,1}
__device__ __forceinline__ void gemm16x16(const float* __restrict__ Ain,
                                          const float* __restrict__ Ws,
                                          int mb, int cb, int lane,
                                          float c[2][4]) {
    int r  = mb * 16 + (lane >> 2);
    int kk = lane & 3;
    const float* ar0 = Ain + r * 68 + kk;
    const float* ar1 = Ain + (r + 8) * 68 + kk;
    const float* bc  = Ws + (cb + (lane >> 2)) * 68 + kk;
    #pragma unroll
    for (int k8 = 0; k8 < 8; k8++) {
        uint32_t a0 = __float_as_uint(ar0[k8 * 8]);
        uint32_t a1 = __float_as_uint(ar1[k8 * 8]);
        uint32_t a2 = __float_as_uint(ar0[k8 * 8 + 4]);
        uint32_t a3 = __float_as_uint(ar1[k8 * 8 + 4]);
        #pragma unroll
        for (int n8 = 0; n8 < 2; n8++) {
            uint32_t b0 = __float_as_uint(bc[n8 * 8 * 68 + k8 * 8]);
            uint32_t b1 = __float_as_uint(bc[n8 * 8 * 68 + k8 * 8 + 4]);
            mma_tf32(c[n8], a0, a1, a2, a3, b0, b1);
        }
    }
}

// =====================================================================
// Kernel A: encoder + decoder + effective L1 bias (fp32 exact)
// =====================================================================
__global__ void setup_kernel(
    const float* __restrict__ poses, const float* __restrict__ t_ped,
    const float* __restrict__ w,
    const float* __restrict__ Wec1, const float* __restrict__ bec1,
    const float* __restrict__ Wec21, const float* __restrict__ bec21,
    const float* __restrict__ Wec22, const float* __restrict__ bec22,
    const float* __restrict__ Wdc1, const float* __restrict__ bdc1,
    const float* __restrict__ Wdc21, const float* __restrict__ bdc21,
    const float* __restrict__ Wdc22, const float* __restrict__ bdc22,
    const float* __restrict__ Wf1, const float* __restrict__ bf1,
    float* __restrict__ out)
{
    int n = blockIdx.x;
    int t = threadIdx.x;
    __shared__ float s_in[88], s_net[64], s_mean[8], s_din[80], s_net2[64], s_ei[32];

    if (t < 72)       s_in[t] = w[n * 24 + t / 3] * poses[n * 72 + t];
    else if (t < 88)  s_in[t] = t_ped[t - 72];
    __syncthreads();

    if (t < 64) {
        float a = bec1[n * 64 + t];
        const float* Wr = &Wec1[(n * 64 + t) * 88];
        #pragma unroll 8
        for (int c = 0; c < 88; c++) a += Wr[c] * s_in[c];
        s_net[t] = fmaxf(a, 0.f);
    }
    __syncthreads();

    if (t < 8) {
        float m = bec21[n * 8 + t], lv = bec22[n * 8 + t];
        const float* Wm = &Wec21[(n * 8 + t) * 64];
        const float* Wl = &Wec22[(n * 8 + t) * 64];
        #pragma unroll 8
        for (int c = 0; c < 64; c++) { m += Wm[c] * s_net[c]; lv += Wl[c] * s_net[c]; }
        s_mean[t] = m;
        out[OFF_MEAN + n * 8 + t] = m;
        out[OFF_LOGVAR + n * 8 + t] = lv;
    }
    __syncthreads();

    if (t < 72)      s_din[t] = s_in[t];
    else if (t < 80) s_din[t] = s_mean[t - 72];
    __syncthreads();

    if (t < 64) {
        float a = bdc1[n * 64 + t];
        const float* Wr = &Wdc1[(n * 64 + t) * 80];
        #pragma unroll 8
        for (int c = 0; c < 80; c++) a += Wr[c] * s_din[c];
        s_net2[t] = fmaxf(a, 0.f);
    }
    __syncthreads();

    if (t < 32) {
        float a = bdc21[n * 32 + t];
        const float* Wr = &Wdc21[(n * 32 + t) * 64];
        #pragma unroll 8
        for (int c = 0; c < 64; c++) a += Wr[c] * s_net2[c];
        s_ei[t] = a;
        g_ei[n * 32 + t] = a;
        out[OFF_EI + n * 32 + t] = a;
    }
    if (t >= 32 && t < 35) {
        int j = t - 32;
        float a = bdc22[n * 3 + j];
        const float* Wr = &Wdc22[(n * 3 + j) * 64];
        #pragma unroll 8
        for (int c = 0; c < 64; c++) a += Wr[c] * s_net2[c];
        out[OFF_DELTA + n * 3 + j] = a;
    }
    __syncthreads();

    if (t < 64) {
        float a = bf1[n * 64 + t];
        const float* Wr = &Wf1[(size_t)(n * 64 + t) * 95];
        #pragma unroll 8
        for (int c = 0; c < 32; c++) a += Wr[c] * s_ei[c];
        g_b1eff[n * 64 + t] = a;
    }
}

// =====================================================================
// Kernel B: RBF blend weights, normalized (fp32 exact)
// =====================================================================
__global__ void bweight_kernel(const float* __restrict__ wpts,
                               const float* __restrict__ nodes_posed)
{
    int v = blockIdx.x * blockDim.x + threadIdx.x;
    if (v >= V_PTS) return;
    float px = wpts[v * 3 + 0], py = wpts[v * 3 + 1], pz = wpts[v * 3 + 2];
    float denom = 0.f;
    for (int n = 0; n < N_NODES; n++) {
        float dx = px - nodes_posed[n * 3 + 0];
        float dy = py - nodes_posed[n * 3 + 1];
        float dz = pz - nodes_posed[n * 3 + 2];
        float d2 = dx * dx + dy * dy + dz * dz;
        float influ = expf(-d2 * (1.0f / 0.18f)) - 0.01f;
        float e = (influ >= 0.f) ? (influ + 1e-7f) : 0.f;
        denom += fmaxf(influ, 0.f) + 1e-7f;
        g_e[n * V_PTS + v] = e;
    }
    float inv = 1.0f / denom;
    for (int n = 0; n < N_NODES; n++) g_e[n * V_PTS + v] *= inv;
}

// =====================================================================
// Kernel E: prepack weights -> tf32, stride-68 padded rows
// =====================================================================
__global__ void prepack_kernel(const float* __restrict__ Wf1,
                               const float* __restrict__ Wf2,
                               const float* __restrict__ Wf3,
                               const float* __restrict__ Wf4)
{
    int n = blockIdx.x, tid = threadIdx.x;   // 256 threads
    float* dst = (float*)&g_Wpad4[(size_t)n * 7616];

    for (int i = tid; i < 4352; i += 256) {            // W1 [64 x 68]
        int j = i / 68, k = i - j * 68;
        float v = (k < XYZ) ? Wf1[(size_t)(n * 64 + j) * 95 + 32 + k] : 0.f;
        dst[i] = to_tf32(v);
    }
    for (int i = tid; i < 4352; i += 256) {            // W2
        int j = i / 68, k = i - j * 68;
        float v = (k < 64) ? Wf2[(size_t)n * 4096 + j * 64 + k] : 0.f;
        dst[4352 + i] = to_tf32(v);
    }
    for (int i = tid; i < 4352; i += 256) {            // W3
        int j = i / 68, k = i - j * 68;
        float v = (k < 64) ? Wf3[(size_t)n * 4096 + j * 64 + k] : 0.f;
        dst[8704 + i] = to_tf32(v);
    }
    for (int i = tid; i < 17408; i += 256) {           // W4 [256 x 68]
        int j = i / 68, k = i - j * 68;
        float v = (k < 64) ? Wf4[(size_t)n * 16384 + j * 64 + k] : 0.f;
        dst[13056 + i] = to_tf32(v);
    }
}

// =====================================================================
// Kernel C: feature field via mma.sync tf32 (HMMA)
// grid = (16 v-tiles) x (9 node-groups), 1024 threads (32 warps)
// 8 mb (16-row blocks) x 4 nq (16-col blocks) -> occ 50%, 8 warps/SMSP
// =====================================================================
__global__ void __launch_bounds__(1024, 1) field_kernel(
    const float* __restrict__ local_coords,
    const float* __restrict__ bf2, const float* __restrict__ bf3,
    const float* __restrict__ bf4)
{
    extern __shared__ float sm[];
    int tid  = threadIdx.x;
    int wid  = tid >> 5, lane = tid & 31;
    int mb   = wid & 7;            // M-block (16 rows)
    int nq   = wid >> 3;           // 0..3: which 16-col block within 64
    int v0 = blockIdx.x * 128;
    int g  = blockIdx.y;
    int n0 = g * 15;
    int ncnt = (g == 8) ? 8 : 15;
    int cb = nq * 16;

    // blend accumulator: rows (mb*16 + lane>>2) and +8; cols nq*16.. per round
    float acc[32];
    #pragma unroll
    for (int i = 0; i < 32; i++) acc[i] = 0.f;

    int r0 = mb * 16 + (lane >> 2);
    int q2 = (lane & 3) * 2;

    for (int ni = 0; ni < ncnt; ni++) {
        int n = n0 + ni;
        __syncthreads();   // previous node's reads done before overwrite

        // ---- stage weights (raw float4 copy of prepacked image) ----
        {
            const float4* src = &g_Wpad4[(size_t)n * 7616];
            float4* dst = ((float4*)sm) + (F_W1 / 4);
            #pragma unroll 4
            for (int i = tid; i < 7616; i += 1024) dst[i] = src[i];
        }
        if (tid < 64) {
            sm[F_B1 + tid] = g_b1eff[n * 64 + tid];
            sm[F_B2 + tid] = bf2[n * 64 + tid];
            sm[F_B3 + tid] = bf3[n * 64 + tid];
        }
        if (tid < 256) sm[F_B4 + tid] = bf4[n * 256 + tid];
        if (tid < 128) sm[F_E + tid]  = g_e[(size_t)n * V_PTS + v0 + tid];
        // ---- stage A0 = lc tile [128 x 64] tf32 (col 63 zero) ----
        for (int i = tid; i < 8192; i += 1024) {
            int v = i >> 6, k = i & 63;
            float val = (k < XYZ)
                ? local_coords[((size_t)n * V_PTS + v0 + v) * XYZ + k] : 0.f;
            sm[F_BUFA + v * 68 + k] = to_tf32(val);
        }
        __syncthreads();

        float ev0 = sm[F_E + r0];
        float ev1 = sm[F_E + r0 + 8];

        // ================= L1: bufA -> bufB =================
        {
            float c[2][4];
            #pragma unroll
            for (int a = 0; a < 2; a++)
                #pragma unroll
                for (int b = 0; b < 4; b++) c[a][b] = 0.f;
            gemm16x16(sm + F_BUFA, sm + F_W1, mb, cb, lane, c);
            #pragma unroll
            for (int n8 = 0; n8 < 2; n8++) {
                int cc = cb + n8 * 8 + q2;
                float b0 = sm[F_B1 + cc], b1 = sm[F_B1 + cc + 1];
                sm[F_BUFB + r0 * 68 + cc]           = to_tf32(fmaxf(c[n8][0] + b0, 0.f));
                sm[F_BUFB + r0 * 68 + cc + 1]       = to_tf32(fmaxf(c[n8][1] + b1, 0.f));
                sm[F_BUFB + (r0 + 8) * 68 + cc]     = to_tf32(fmaxf(c[n8][2] + b0, 0.f));
                sm[F_BUFB + (r0 + 8) * 68 + cc + 1] = to_tf32(fmaxf(c[n8][3] + b1, 0.f));
            }
        }
        __syncthreads();

        // ================= L2: bufB -> bufA =================
        {
            float c[2][4];
            #pragma unroll
            for (int a = 0; a < 2; a++)
                #pragma unroll
                for (int b = 0; b < 4; b++) c[a][b] = 0.f;
            gemm16x16(sm + F_BUFB, sm + F_W2, mb, cb, lane, c);
            #pragma unroll
            for (int n8 = 0; n8 < 2; n8++) {
                int cc = cb + n8 * 8 + q2;
                float b0 = sm[F_B2 + cc], b1 = sm[F_B2 + cc + 1];
                sm[F_BUFA + r0 * 68 + cc]           = to_tf32(fmaxf(c[n8][0] + b0, 0.f));
                sm[F_BUFA + r0 * 68 + cc + 1]       = to_tf32(fmaxf(c[n8][1] + b1, 0.f));
                sm[F_BUFA + (r0 + 8) * 68 + cc]     = to_tf32(fmaxf(c[n8][2] + b0, 0.f));
                sm[F_BUFA + (r0 + 8) * 68 + cc + 1] = to_tf32(fmaxf(c[n8][3] + b1, 0.f));
            }
        }
        __syncthreads();

        // ================= L3: bufA -> bufB =================
        {
            float c[2][4];
            #pragma unroll
            for (int a = 0; a < 2; a++)
                #pragma unroll
                for (int b = 0; b < 4; b++) c[a][b] = 0.f;
            gemm16x16(sm + F_BUFA, sm + F_W3, mb, cb, lane, c);
            #pragma unroll
            for (int n8 = 0; n8 < 2; n8++) {
                int cc = cb + n8 * 8 + q2;
                float b0 = sm[F_B3 + cc], b1 = sm[F_B3 + cc + 1];
                sm[F_BUFB + r0 * 68 + cc]           = to_tf32(fmaxf(c[n8][0] + b0, 0.f));
                sm[F_BUFB + r0 * 68 + cc + 1]       = to_tf32(fmaxf(c[n8][1] + b1, 0.f));
                sm[F_BUFB + (r0 + 8) * 68 + cc]     = to_tf32(fmaxf(c[n8][2] + b0, 0.f));
                sm[F_BUFB + (r0 + 8) * 68 + cc + 1] = to_tf32(fmaxf(c[n8][3] + b1, 0.f));
            }
        }
        __syncthreads();

        // ================= L4: bufB x W4 (256 cols, 4 rounds of 64) =================
        #pragma unroll
        for (int rnd = 0; rnd < 4; rnd++) {
            float c[2][4];
            #pragma unroll
            for (int a = 0; a < 2; a++)
                #pragma unroll
                for (int b = 0; b < 4; b++) c[a][b] = 0.f;
            int cb4 = rnd * 64 + cb;
            gemm16x16(sm + F_BUFB, sm + F_W4, mb, cb4, lane, c);
            #pragma unroll
            for (int n8 = 0; n8 < 2; n8++) {
                int cc = cb4 + n8 * 8 + q2;
                float b0 = sm[F_B4 + cc], b1 = sm[F_B4 + cc + 1];
                int ai = rnd * 8 + n8 * 4;
                acc[ai + 0] += ev0 * fmaxf(c[n8][0] + b0, 0.f);
                acc[ai + 1] += ev0 * fmaxf(c[n8][1] + b1, 0.f);
                acc[ai + 2] += ev1 * fmaxf(c[n8][2] + b0, 0.f);
                acc[ai + 3] += ev1 * fmaxf(c[n8][3] + b1, 0.f);
            }
        }
        // loop-top __syncthreads() covers L4-read completion before restage
    }

    // ---- write this group's partial tile ----
    {
        size_t base0 = ((size_t)g * V_PTS + v0 + r0) * 256;
        size_t base1 = ((size_t)g * V_PTS + v0 + r0 + 8) * 256;
        #pragma unroll
        for (int rnd = 0; rnd < 4; rnd++) {
            #pragma unroll
            for (int n8 = 0; n8 < 2; n8++) {
                int cc = rnd * 64 + cb + n8 * 8 + q2;
                int ai = rnd * 8 + n8 * 4;
                *(float2*)&g_fpart[base0 + cc] = make_float2(acc[ai + 0], acc[ai + 1]);
                *(float2*)&g_fpart[base1 + cc] = make_float2(acc[ai + 2], acc[ai + 3]);
            }
        }
    }
}

// =====================================================================
// Kernel D: reduce partials + NeRF head
// =====================================================================
__global__ void head_kernel(const float* __restrict__ Wc1, const float* __restrict__ bc1,
                            const float* __restrict__ Wc2, const float* __restrict__ bc2,
                            const float* __restrict__ Wd1, const float* __restrict__ bd1,
                            float* __restrict__ out)
{
    int v = blockIdx.x;
    int t = threadIdx.x;   // 64 threads
    __shared__ float f_s[256];
    __shared__ float netc_s[64];

    {
        float4 s = make_float4(0.f, 0.f, 0.f, 0.f);
        #pragma unroll
        for (int g2 = 0; g2 < NG; g2++) {
            float4 p = *(const float4*)&g_fpart[((size_t)g2 * V_PTS + v) * 256 + t * 4];
            s.x += p.x; s.y += p.y; s.z += p.z; s.w += p.w;
        }
        *(float4*)&f_s[t * 4] = s;
    }
    __syncthreads();

    {
        float a0 = 0.f, a1 = 0.f, a2 = 0.f, a3 = 0.f;
        #pragma unroll 8
        for (int c = 0; c < 256; c += 4) {
            a0 += f_s[c + 0] * Wc1[(c + 0) * 64 + t];
            a1 += f_s[c + 1] * Wc1[(c + 1) * 64 + t];
            a2 += f_s[c + 2] * Wc1[(c + 2) * 64 + t];
            a3 += f_s[c + 3] * Wc1[(c + 3) * 64 + t];
        }
        netc_s[t] = fmaxf(bc1[t] + ((a0 + a1) + (a2 + a3)), 0.f);
    }
    __syncthreads();

    if (t < 3) {
        float r = bc2[t];
        #pragma unroll 8
        for (int j = 0; j < 64; j++) r += netc_s[j] * Wc2[j * 3 + t];
        out[OFF_C + v * 3 + t] = r;
    } else if (t == 3) {
        float r0 = 0.f, r1 = 0.f, r2 = 0.f, r3 = 0.f;
        #pragma unroll 8
        for (int c = 0; c < 256; c += 4) {
            r0 += f_s[c + 0] * Wd1[c + 0];
            r1 += f_s[c + 1] * Wd1[c + 1];
            r2 += f_s[c + 2] * Wd1[c + 2];
            r3 += f_s[c + 3] * Wd1[c + 3];
        }
        out[OFF_D + v] = fmaxf(bd1[0] + ((r0 + r1) + (r2 + r3)), 0.f);
    }
}

// =====================================================================
extern "C" void kernel_launch(void* const* d_in, const int* in_sizes, int n_in,
                              void* d_out, int out_size)
{
    const float* poses = (const float*)d_in[0];
    const float* t_ped = (const float*)d_in[1];
    const float* w     = (const float*)d_in[2];
    const float* wpts  = (const float*)d_in[3];
    const float* nodes = (const float*)d_in[4];
    const float* lc    = (const float*)d_in[5];
    const float *Wec1 = (const float*)d_in[6],  *bec1 = (const float*)d_in[7];
    const float *Wec21= (const float*)d_in[8],  *bec21= (const float*)d_in[9];
    const float *Wec22= (const float*)d_in[10], *bec22= (const float*)d_in[11];
    const float *Wdc1 = (const float*)d_in[12], *bdc1 = (const float*)d_in[13];
    const float *Wdc21= (const float*)d_in[14], *bdc21= (const float*)d_in[15];
    const float *Wdc22= (const float*)d_in[16], *bdc22= (const float*)d_in[17];
    const float *Wf1  = (const float*)d_in[18], *bf1  = (const float*)d_in[19];
    const float *Wf2  = (const float*)d_in[20], *bf2  = (const float*)d_in[21];
    const float *Wf3  = (const float*)d_in[22], *bf3  = (const float*)d_in[23];
    const float *Wf4  = (const float*)d_in[24], *bf4  = (const float*)d_in[25];
    const float *Wc1  = (const float*)d_in[26], *bc1  = (const float*)d_in[27];
    const float *Wc2  = (const float*)d_in[28], *bc2  = (const float*)d_in[29];
    const float *Wd1  = (const float*)d_in[30], *bd1  = (const float*)d_in[31];
    float* out = (float*)d_out;

    setup_kernel<<<N_NODES, 128>>>(poses, t_ped, w,
                                   Wec1, bec1, Wec21, bec21, Wec22, bec22,
                                   Wdc1, bdc1, Wdc21, bdc21, Wdc22, bdc22,
                                   Wf1, bf1, out);
    bweight_kernel<<<V_PTS / 256, 256>>>(wpts, nodes);
    prepack_kernel<<<N_NODES, 256>>>(Wf1, Wf2, Wf3, Wf4);

    cudaFuncSetAttribute(field_kernel,
                         cudaFuncAttributeMaxDynamicSharedMemorySize,
                         F_TOT * (int)sizeof(float));
    field_kernel<<<dim3(V_PTS / 128, NG), 1024, F_TOT * sizeof(float)>>>(lc, bf2, bf3, bf4);

    head_kernel<<<V_PTS, 64>>>(Wc1, bc1, Wc2, bc2, Wd1, bd1, out);
}

// round 14
// speedup vs baseline: 1.7870x; 1.4730x over previous
#include <cuda_runtime.h>
#include <cuda_fp16.h>
#include <cstdint>

#define N_NODES 128
#define V_PTS   2048
#define XYZ     63
#define NG      9          // node groups: 8 groups of 15 + 1 group of 8

// ---- output layout ----
#define OFF_C      0
#define OFF_D      6144
#define OFF_EI     8192
#define OFF_DELTA  12288
#define OFF_MEAN   12672
#define OFF_LOGVAR 13696

// ---- scratch ----
__device__ float g_ei[N_NODES * 32];
__device__ float g_b1eff[N_NODES * 64];
__device__ float g_e[N_NODES * V_PTS];
__device__ float g_fpart[NG * V_PTS * 256];
// per-node packed weight image: f16, row stride 72 halves
// W1 [64x72] | W2 | W3 | W4 [256x72] => 32256 halves = 64512 B = 4032 float4 per node
__device__ float4 g_Wpad4[N_NODES * 4032];

// ---- field smem layout (BYTE offsets) ----
#define FB_BUFA 0         // 128 x 72 f16
#define FB_BUFB 18432
#define FB_W1   36864     // 64 x 72 f16
#define FB_W2   46080
#define FB_W3   55296
#define FB_W4   64512     // 256 x 72 f16
#define FB_B1   101376    // f32 x 64
#define FB_B2   101632
#define FB_B3   101888
#define FB_B4   102144    // f32 x 256
#define FB_E    103168    // f32 x 128
#define FB_TOT  103680

__device__ __forceinline__ void mma_f16(float c[4], uint32_t a0, uint32_t a1,
                                        uint32_t a2, uint32_t a3,
                                        uint32_t b0, uint32_t b1) {
    asm volatile(
        "mma.sync.aligned.m16n8k16.row.col.f32.f16.f16.f32 "
        "{%0,%1,%2,%3}, {%4,%5,%6,%7}, {%8,%9}, {%0,%1,%2,%3};"
        : "+f"(c[0]), "+f"(c[1]), "+f"(c[2]), "+f"(c[3])
        : "r"(a0), "r"(a1), "r"(a2), "r"(a3), "r"(b0), "r"(b1));
}

// one warp computes a 16x32 tile of C[128 x N] = A[128 x 64] * W[N x 64]^T, f16 inputs
// word layout: rows of 36 u32 (72 f16). a0={A[r][2q],A[r][2q+1]}, a2=cols+8; b likewise.
__device__ __forceinline__ void gemm16x32_f16(const uint32_t* __restrict__ Ain,
                                              const uint32_t* __restrict__ Ws,
                                              int mb, int cb, int lane,
                                              float c[4][4]) {
    int r = mb * 16 + (lane >> 2);
    int q = lane & 3;
    const uint32_t* ar0 = Ain + r * 36 + q;
    const uint32_t* ar1 = ar0 + 8 * 36;
    const uint32_t* bc  = Ws + (cb + (lane >> 2)) * 36 + q;
    #pragma unroll
    for (int ks = 0; ks < 4; ks++) {           // 4 k16 steps (K=64)
        uint32_t a0 = ar0[ks * 8];
        uint32_t a1 = ar1[ks * 8];
        uint32_t a2 = ar0[ks * 8 + 4];
        uint32_t a3 = ar1[ks * 8 + 4];
        #pragma unroll
        for (int n8 = 0; n8 < 4; n8++) {
            uint32_t b0 = bc[n8 * 8 * 36 + ks * 8];
            uint32_t b1 = bc[n8 * 8 * 36 + ks * 8 + 4];
            mma_f16(c[n8], a0, a1, a2, a3, b0, b1);
        }
    }
}

// =====================================================================
// Kernel A: encoder + decoder + effective L1 bias (fp32 exact)
// =====================================================================
__global__ void setup_kernel(
    const float* __restrict__ poses, const float* __restrict__ t_ped,
    const float* __restrict__ w,
    const float* __restrict__ Wec1, const float* __restrict__ bec1,
    const float* __restrict__ Wec21, const float* __restrict__ bec21,
    const float* __restrict__ Wec22, const float* __restrict__ bec22,
    const float* __restrict__ Wdc1, const float* __restrict__ bdc1,
    const float* __restrict__ Wdc21, const float* __restrict__ bdc21,
    const float* __restrict__ Wdc22, const float* __restrict__ bdc22,
    const float* __restrict__ Wf1, const float* __restrict__ bf1,
    float* __restrict__ out)
{
    int n = blockIdx.x;
    int t = threadIdx.x;
    __shared__ float s_in[88], s_net[64], s_mean[8], s_din[80], s_net2[64], s_ei[32];

    if (t < 72)       s_in[t] = w[n * 24 + t / 3] * poses[n * 72 + t];
    else if (t < 88)  s_in[t] = t_ped[t - 72];
    __syncthreads();

    if (t < 64) {
        float a = bec1[n * 64 + t];
        const float* Wr = &Wec1[(n * 64 + t) * 88];
        #pragma unroll 8
        for (int c = 0; c < 88; c++) a += Wr[c] * s_in[c];
        s_net[t] = fmaxf(a, 0.f);
    }
    __syncthreads();

    if (t < 8) {
        float m = bec21[n * 8 + t], lv = bec22[n * 8 + t];
        const float* Wm = &Wec21[(n * 8 + t) * 64];
        const float* Wl = &Wec22[(n * 8 + t) * 64];
        #pragma unroll 8
        for (int c = 0; c < 64; c++) { m += Wm[c] * s_net[c]; lv += Wl[c] * s_net[c]; }
        s_mean[t] = m;
        out[OFF_MEAN + n * 8 + t] = m;
        out[OFF_LOGVAR + n * 8 + t] = lv;
    }
    __syncthreads();

    if (t < 72)      s_din[t] = s_in[t];
    else if (t < 80) s_din[t] = s_mean[t - 72];
    __syncthreads();

    if (t < 64) {
        float a = bdc1[n * 64 + t];
        const float* Wr = &Wdc1[(n * 64 + t) * 80];
        #pragma unroll 8
        for (int c = 0; c < 80; c++) a += Wr[c] * s_din[c];
        s_net2[t] = fmaxf(a, 0.f);
    }
    __syncthreads();

    if (t < 32) {
        float a = bdc21[n * 32 + t];
        const float* Wr = &Wdc21[(n * 32 + t) * 64];
        #pragma unroll 8
        for (int c = 0; c < 64; c++) a += Wr[c] * s_net2[c];
        s_ei[t] = a;
        g_ei[n * 32 + t] = a;
        out[OFF_EI + n * 32 + t] = a;
    }
    if (t >= 32 && t < 35) {
        int j = t - 32;
        float a = bdc22[n * 3 + j];
        const float* Wr = &Wdc22[(n * 3 + j) * 64];
        #pragma unroll 8
        for (int c = 0; c < 64; c++) a += Wr[c] * s_net2[c];
        out[OFF_DELTA + n * 3 + j] = a;
    }
    __syncthreads();

    if (t < 64) {
        float a = bf1[n * 64 + t];
        const float* Wr = &Wf1[(size_t)(n * 64 + t) * 95];
        #pragma unroll 8
        for (int c = 0; c < 32; c++) a += Wr[c] * s_ei[c];
        g_b1eff[n * 64 + t] = a;
    }
}

// =====================================================================
// Kernel E+B merged: blocks 0..127 prepack weights -> f16 images,
//                    blocks 128..135 compute RBF blend weights.
// 256 threads.
// =====================================================================
__global__ void prep_kernel(const float* __restrict__ Wf1,
                            const float* __restrict__ Wf2,
                            const float* __restrict__ Wf3,
                            const float* __restrict__ Wf4,
                            const float* __restrict__ wpts,
                            const float* __restrict__ nodes_posed)
{
    int bid = blockIdx.x, tid = threadIdx.x;
    if (bid < N_NODES) {
        int n = bid;
        __half* dst = (__half*)&g_Wpad4[(size_t)n * 4032];

        for (int i = tid; i < 4608; i += 256) {            // W1 [64 x 72]
            int j = i / 72, k = i - j * 72;
            float v = (k < XYZ) ? Wf1[(size_t)(n * 64 + j) * 95 + 32 + k] : 0.f;
            dst[i] = __float2half_rn(v);
        }
        for (int i = tid; i < 4608; i += 256) {            // W2
            int j = i / 72, k = i - j * 72;
            float v = (k < 64) ? Wf2[(size_t)n * 4096 + j * 64 + k] : 0.f;
            dst[4608 + i] = __float2half_rn(v);
        }
        for (int i = tid; i < 4608; i += 256) {            // W3
            int j = i / 72, k = i - j * 72;
            float v = (k < 64) ? Wf3[(size_t)n * 4096 + j * 64 + k] : 0.f;
            dst[9216 + i] = __float2half_rn(v);
        }
        for (int i = tid; i < 18432; i += 256) {           // W4 [256 x 72]
            int j = i / 72, k = i - j * 72;
            float v = (k < 64) ? Wf4[(size_t)n * 16384 + j * 64 + k] : 0.f;
            dst[13824 + i] = __float2half_rn(v);
        }
    } else {
        int v = (bid - N_NODES) * 256 + tid;
        if (v >= V_PTS) return;
        float px = wpts[v * 3 + 0], py = wpts[v * 3 + 1], pz = wpts[v * 3 + 2];
        float denom = 0.f;
        for (int n = 0; n < N_NODES; n++) {
            float dx = px - nodes_posed[n * 3 + 0];
            float dy = py - nodes_posed[n * 3 + 1];
            float dz = pz - nodes_posed[n * 3 + 2];
            float d2 = dx * dx + dy * dy + dz * dz;
            float influ = expf(-d2 * (1.0f / 0.18f)) - 0.01f;
            float e = (influ >= 0.f) ? (influ + 1e-7f) : 0.f;
            denom += fmaxf(influ, 0.f) + 1e-7f;
            g_e[n * V_PTS + v] = e;
        }
        float inv = 1.0f / denom;
        for (int n = 0; n < N_NODES; n++) g_e[n * V_PTS + v] *= inv;
    }
}

// =====================================================================
// Kernel C: feature field via mma.sync f16 (m16n8k16 HMMA)
// grid = (16 v-tiles) x (9 node-groups), 512 threads (16 warps)
// =====================================================================
__global__ void __launch_bounds__(512, 1) field_kernel(
    const float* __restrict__ local_coords,
    const float* __restrict__ bf2, const float* __restrict__ bf3,
    const float* __restrict__ bf4)
{
    extern __shared__ char smc[];
    __half*  smh = (__half*)smc;
    uint32_t* smw = (uint32_t*)smc;
    float*   smf = (float*)smc;

    int tid  = threadIdx.x;
    int wid  = tid >> 5, lane = tid & 31;
    int mb   = wid & 7;            // M-block (16 rows)
    int nhi  = wid >> 3;           // 0/1: which 32-col block within 64
    int v0 = blockIdx.x * 128;
    int g  = blockIdx.y;
    int n0 = g * 15;
    int ncnt = (g == 8) ? 8 : 15;
    int cb = nhi * 32;

    float acc[64];
    #pragma unroll
    for (int i = 0; i < 64; i++) acc[i] = 0.f;

    int r0 = mb * 16 + (lane >> 2);
    int q  = lane & 3;
    int q2 = q * 2;

    for (int ni = 0; ni < ncnt; ni++) {
        int n = n0 + ni;
        __syncthreads();   // previous node's reads done before overwrite

        // ---- stage f16 weight image (raw float4 copy) ----
        {
            const float4* src = &g_Wpad4[(size_t)n * 4032];
            float4* dst = (float4*)(smc + FB_W1);
            #pragma unroll 4
            for (int i = tid; i < 4032; i += 512) dst[i] = src[i];
        }
        if (tid < 64) {
            smf[FB_B1 / 4 + tid] = g_b1eff[n * 64 + tid];
            smf[FB_B2 / 4 + tid] = bf2[n * 64 + tid];
            smf[FB_B3 / 4 + tid] = bf3[n * 64 + tid];
        }
        if (tid < 256) smf[FB_B4 / 4 + tid] = bf4[n * 256 + tid];
        if (tid < 128) smf[FB_E / 4 + tid]  = g_e[(size_t)n * V_PTS + v0 + tid];
        // ---- stage A0 = lc tile [128 x 64] f16 (col 63 zero) ----
        for (int i = tid; i < 8192; i += 512) {
            int v = i >> 6, k = i & 63;
            float val = (k < XYZ)
                ? local_coords[((size_t)n * V_PTS + v0 + v) * XYZ + k] : 0.f;
            smh[FB_BUFA / 2 + v * 72 + k] = __float2half_rn(val);
        }
        __syncthreads();

        float ev0 = smf[FB_E / 4 + r0];
        float ev1 = smf[FB_E / 4 + r0 + 8];

        const uint32_t* wA = smw + FB_BUFA / 4;
        const uint32_t* wB = smw + FB_BUFB / 4;

        // ================= L1: bufA -> bufB =================
        {
            float c[4][4];
            #pragma unroll
            for (int a = 0; a < 4; a++)
                #pragma unroll
                for (int b = 0; b < 4; b++) c[a][b] = 0.f;
            gemm16x32_f16(wA, smw + FB_W1 / 4, mb, cb, lane, c);
            #pragma unroll
            for (int n8 = 0; n8 < 4; n8++) {
                int cc = cb + n8 * 8 + q2;
                float b0 = smf[FB_B1 / 4 + cc], b1 = smf[FB_B1 / 4 + cc + 1];
                ((__half2*)smc)[FB_BUFB / 4 + r0 * 36 + (cc >> 1)] =
                    __floats2half2_rn(fmaxf(c[n8][0] + b0, 0.f), fmaxf(c[n8][1] + b1, 0.f));
                ((__half2*)smc)[FB_BUFB / 4 + (r0 + 8) * 36 + (cc >> 1)] =
                    __floats2half2_rn(fmaxf(c[n8][2] + b0, 0.f), fmaxf(c[n8][3] + b1, 0.f));
            }
        }
        __syncthreads();

        // ================= L2: bufB -> bufA =================
        {
            float c[4][4];
            #pragma unroll
            for (int a = 0; a < 4; a++)
                #pragma unroll
                for (int b = 0; b < 4; b++) c[a][b] = 0.f;
            gemm16x32_f16(wB, smw + FB_W2 / 4, mb, cb, lane, c);
            #pragma unroll
            for (int n8 = 0; n8 < 4; n8++) {
                int cc = cb + n8 * 8 + q2;
                float b0 = smf[FB_B2 / 4 + cc], b1 = smf[FB_B2 / 4 + cc + 1];
                ((__half2*)smc)[FB_BUFA / 4 + r0 * 36 + (cc >> 1)] =
                    __floats2half2_rn(fmaxf(c[n8][0] + b0, 0.f), fmaxf(c[n8][1] + b1, 0.f));
                ((__half2*)smc)[FB_BUFA / 4 + (r0 + 8) * 36 + (cc >> 1)] =
                    __floats2half2_rn(fmaxf(c[n8][2] + b0, 0.f), fmaxf(c[n8][3] + b1, 0.f));
            }
        }
        __syncthreads();

        // ================= L3: bufA -> bufB =================
        {
            float c[4][4];
            #pragma unroll
            for (int a = 0; a < 4; a++)
                #pragma unroll
                for (int b = 0; b < 4; b++) c[a][b] = 0.f;
            gemm16x32_f16(wA, smw + FB_W3 / 4, mb, cb, lane, c);
            #pragma unroll
            for (int n8 = 0; n8 < 4; n8++) {
                int cc = cb + n8 * 8 + q2;
                float b0 = smf[FB_B3 / 4 + cc], b1 = smf[FB_B3 / 4 + cc + 1];
                ((__half2*)smc)[FB_BUFB / 4 + r0 * 36 + (cc >> 1)] =
                    __floats2half2_rn(fmaxf(c[n8][0] + b0, 0.f), fmaxf(c[n8][1] + b1, 0.f));
                ((__half2*)smc)[FB_BUFB / 4 + (r0 + 8) * 36 + (cc >> 1)] =
                    __floats2half2_rn(fmaxf(c[n8][2] + b0, 0.f), fmaxf(c[n8][3] + b1, 0.f));
            }
        }
        __syncthreads();

        // ================= L4: bufB x W4 (256 cols, 4 rounds) =================
        #pragma unroll
        for (int rnd = 0; rnd < 4; rnd++) {
            float c[4][4];
            #pragma unroll
            for (int a = 0; a < 4; a++)
                #pragma unroll
                for (int b = 0; b < 4; b++) c[a][b] = 0.f;
            int cb4 = rnd * 64 + cb;
            gemm16x32_f16(wB, smw + FB_W4 / 4, mb, cb4, lane, c);
            #pragma unroll
            for (int n8 = 0; n8 < 4; n8++) {
                int cc = cb4 + n8 * 8 + q2;
                float b0 = smf[FB_B4 / 4 + cc], b1 = smf[FB_B4 / 4 + cc + 1];
                int ai = rnd * 16 + n8 * 4;
                acc[ai + 0] += ev0 * fmaxf(c[n8][0] + b0, 0.f);
                acc[ai + 1] += ev0 * fmaxf(c[n8][1] + b1, 0.f);
                acc[ai + 2] += ev1 * fmaxf(c[n8][2] + b0, 0.f);
                acc[ai + 3] += ev1 * fmaxf(c[n8][3] + b1, 0.f);
            }
        }
        // loop-top __syncthreads() covers L4-read completion before restage
    }

    // ---- write this group's partial tile ----
    {
        size_t base0 = ((size_t)g * V_PTS + v0 + r0) * 256;
        size_t base1 = ((size_t)g * V_PTS + v0 + r0 + 8) * 256;
        #pragma unroll
        for (int rnd = 0; rnd < 4; rnd++) {
            #pragma unroll
            for (int n8 = 0; n8 < 4; n8++) {
                int cc = rnd * 64 + cb + n8 * 8 + q2;
                int ai = rnd * 16 + n8 * 4;
                *(float2*)&g_fpart[base0 + cc] = make_float2(acc[ai + 0], acc[ai + 1]);
                *(float2*)&g_fpart[base1 + cc] = make_float2(acc[ai + 2], acc[ai + 3]);
            }
        }
    }
}

// =====================================================================
// Kernel D: reduce partials + NeRF head. 4 points per block, 256 thr.
// =====================================================================
__global__ void head_kernel(const float* __restrict__ Wc1, const float* __restrict__ bc1,
                            const float* __restrict__ Wc2, const float* __restrict__ bc2,
                            const float* __restrict__ Wd1, const float* __restrict__ bd1,
                            float* __restrict__ out)
{
    int sub = threadIdx.x >> 6;       // 0..3
    int t   = threadIdx.x & 63;
    int v   = blockIdx.x * 4 + sub;
    __shared__ float f_s[4][256];
    __shared__ float netc_s[4][64];

    {
        float4 s = make_float4(0.f, 0.f, 0.f, 0.f);
        #pragma unroll
        for (int g2 = 0; g2 < NG; g2++) {
            float4 p = *(const float4*)&g_fpart[((size_t)g2 * V_PTS + v) * 256 + t * 4];
            s.x += p.x; s.y += p.y; s.z += p.z; s.w += p.w;
        }
        *(float4*)&f_s[sub][t * 4] = s;
    }
    __syncthreads();

    {
        float a0 = 0.f, a1 = 0.f, a2 = 0.f, a3 = 0.f;
        #pragma unroll 8
        for (int c = 0; c < 256; c += 4) {
            a0 += f_s[sub][c + 0] * Wc1[(c + 0) * 64 + t];
            a1 += f_s[sub][c + 1] * Wc1[(c + 1) * 64 + t];
            a2 += f_s[sub][c + 2] * Wc1[(c + 2) * 64 + t];
            a3 += f_s[sub][c + 3] * Wc1[(c + 3) * 64 + t];
        }
        netc_s[sub][t] = fmaxf(bc1[t] + ((a0 + a1) + (a2 + a3)), 0.f);
    }
    __syncthreads();

    if (t < 3) {
        float r = bc2[t];
        #pragma unroll 8
        for (int j = 0; j < 64; j++) r += netc_s[sub][j] * Wc2[j * 3 + t];
        out[OFF_C + v * 3 + t] = r;
    } else if (t == 3) {
        float r0 = 0.f, r1 = 0.f, r2 = 0.f, r3 = 0.f;
        #pragma unroll 8
        for (int c = 0; c < 256; c += 4) {
            r0 += f_s[sub][c + 0] * Wd1[c + 0];
            r1 += f_s[sub][c + 1] * Wd1[c + 1];
            r2 += f_s[sub][c + 2] * Wd1[c + 2];
            r3 += f_s[sub][c + 3] * Wd1[c + 3];
        }
        out[OFF_D + v] = fmaxf(bd1[0] + ((r0 + r1) + (r2 + r3)), 0.f);
    }
}

// =====================================================================
extern "C" void kernel_launch(void* const* d_in, const int* in_sizes, int n_in,
                              void* d_out, int out_size)
{
    const float* poses = (const float*)d_in[0];
    const float* t_ped = (const float*)d_in[1];
    const float* w     = (const float*)d_in[2];
    const float* wpts  = (const float*)d_in[3];
    const float* nodes = (const float*)d_in[4];
    const float* lc    = (const float*)d_in[5];
    const float *Wec1 = (const float*)d_in[6],  *bec1 = (const float*)d_in[7];
    const float *Wec21= (const float*)d_in[8],  *bec21= (const float*)d_in[9];
    const float *Wec22= (const float*)d_in[10], *bec22= (const float*)d_in[11];
    const float *Wdc1 = (const float*)d_in[12], *bdc1 = (const float*)d_in[13];
    const float *Wdc21= (const float*)d_in[14], *bdc21= (const float*)d_in[15];
    const float *Wdc22= (const float*)d_in[16], *bdc22= (const float*)d_in[17];
    const float *Wf1  = (const float*)d_in[18], *bf1  = (const float*)d_in[19];
    const float *Wf2  = (const float*)d_in[20], *bf2  = (const float*)d_in[21];
    const float *Wf3  = (const float*)d_in[22], *bf3  = (const float*)d_in[23];
    const float *Wf4  = (const float*)d_in[24], *bf4  = (const float*)d_in[25];
    const float *Wc1  = (const float*)d_in[26], *bc1  = (const float*)d_in[27];
    const float *Wc2  = (const float*)d_in[28], *bc2  = (const float*)d_in[29];
    const float *Wd1  = (const float*)d_in[30], *bd1  = (const float*)d_in[31];
    float* out = (float*)d_out;

    setup_kernel<<<N_NODES, 128>>>(poses, t_ped, w,
                                   Wec1, bec1, Wec21, bec21, Wec22, bec22,
                                   Wdc1, bdc1, Wdc21, bdc21, Wdc22, bdc22,
                                   Wf1, bf1, out);
    prep_kernel<<<N_NODES + V_PTS / 256, 256>>>(Wf1, Wf2, Wf3, Wf4, wpts, nodes);

    cudaFuncSetAttribute(field_kernel,
                         cudaFuncAttributeMaxDynamicSharedMemorySize, FB_TOT);
    field_kernel<<<dim3(V_PTS / 128, NG), 512, FB_TOT>>>(lc, bf2, bf3, bf4);

    head_kernel<<<V_PTS / 4, 256>>>(Wc1, bc1, Wc2, bc2, Wd1, bd1, out);
}

// round 15
// speedup vs baseline: 2.1558x; 1.2064x over previous
#include <cuda_runtime.h>
#include <cuda_fp16.h>
#include <cstdint>

#define N_NODES 128
#define V_PTS   2048
#define XYZ     63
#define NG      9          // node groups: 8 groups of 15 + 1 group of 8

// ---- output layout ----
#define OFF_C      0
#define OFF_D      6144
#define OFF_EI     8192
#define OFF_DELTA  12288
#define OFF_MEAN   12672
#define OFF_LOGVAR 13696

// ---- scratch ----
__device__ float g_ei[N_NODES * 32];
__device__ float g_b1eff[N_NODES * 64];
__device__ float g_e[N_NODES * V_PTS];
__device__ float g_fpart[NG * V_PTS * 256];
// per-node packed weight image: f16, row stride 72 halves (4032 float4 per node)
__device__ float4 g_Wpad4[N_NODES * 4032];

// ---- field smem layout (BYTE offsets) ----
#define FB_BUFA  0                         // 128 x 72 f16 = 18432
#define FB_BUFB  18432
#define FB_LCRAW 36864                     // 8068 fp32 words = 32272 B
#define FB_W(b)  (69136 + (b) * 64512)    // f16 weight image, double-buffered
#define FB_BS(b) (198160 + (b) * 2304)    // B1@0 B2@256 B3@512 B4@768 E@1792 (bytes)
#define FB_TOT   202768

__device__ __forceinline__ uint32_t s2u(const void* p) {
    return (uint32_t)__cvta_generic_to_shared(p);
}
#define CP16(d, s) asm volatile("cp.async.ca.shared.global [%0], [%1], 16;" :: "r"(d), "l"(s))
#define CP_COMMIT() asm volatile("cp.async.commit_group;")
#define CP_WAIT0()  asm volatile("cp.async.wait_group 0;" ::: "memory")

__device__ __forceinline__ void mma_f16(float c[4], uint32_t a0, uint32_t a1,
                                        uint32_t a2, uint32_t a3,
                                        uint32_t b0, uint32_t b1) {
    asm volatile(
        "mma.sync.aligned.m16n8k16.row.col.f32.f16.f16.f32 "
        "{%0,%1,%2,%3}, {%4,%5,%6,%7}, {%8,%9}, {%0,%1,%2,%3};"
        : "+f"(c[0]), "+f"(c[1]), "+f"(c[2]), "+f"(c[3])
        : "r"(a0), "r"(a1), "r"(a2), "r"(a3), "r"(b0), "r"(b1));
}

// one warp computes a 16x32 tile of C[128 x N] = A[128 x 64] * W[N x 64]^T, f16
// word layout: rows of 36 u32 (72 f16).
__device__ __forceinline__ void gemm16x32_f16(const uint32_t* __restrict__ Ain,
                                              const uint32_t* __restrict__ Ws,
                                              int mb, int cb, int lane,
                                              float c[4][4]) {
    int r = mb * 16 + (lane >> 2);
    int q = lane & 3;
    const uint32_t* ar0 = Ain + r * 36 + q;
    const uint32_t* ar1 = ar0 + 8 * 36;
    const uint32_t* bc  = Ws + (cb + (lane >> 2)) * 36 + q;
    #pragma unroll
    for (int ks = 0; ks < 4; ks++) {
        uint32_t a0 = ar0[ks * 8];
        uint32_t a1 = ar1[ks * 8];
        uint32_t a2 = ar0[ks * 8 + 4];
        uint32_t a3 = ar1[ks * 8 + 4];
        #pragma unroll
        for (int n8 = 0; n8 < 4; n8++) {
            uint32_t b0 = bc[n8 * 8 * 36 + ks * 8];
            uint32_t b1 = bc[n8 * 8 * 36 + ks * 8 + 4];
            mma_f16(c[n8], a0, a1, a2, a3, b0, b1);
        }
    }
}

// async prefetch of one node's weights/biases/E + raw lc tile
__device__ __forceinline__ void prefetch_node(char* smc, int buf, int n, int v0, int tid,
    const float* __restrict__ bf2, const float* __restrict__ bf3,
    const float* __restrict__ bf4, const float* __restrict__ lc)
{
    uint32_t wdst = s2u(smc + FB_W(buf));
    const float4* wsrc = &g_Wpad4[(size_t)n * 4032];
    #pragma unroll 2
    for (int i = tid; i < 4032; i += 512)
        CP16(wdst + i * 16, wsrc + i);

    uint32_t bdst = s2u(smc + FB_BS(buf));
    if (tid < 144) {
        const float4* src;
        uint32_t d;
        if (tid < 16)       { src = (const float4*)(g_b1eff + n * 64) + tid;                     d = bdst + tid * 16; }
        else if (tid < 32)  { src = (const float4*)(bf2 + n * 64) + (tid - 16);                  d = bdst + 256 + (tid - 16) * 16; }
        else if (tid < 48)  { src = (const float4*)(bf3 + n * 64) + (tid - 32);                  d = bdst + 512 + (tid - 32) * 16; }
        else if (tid < 112) { src = (const float4*)(bf4 + n * 256) + (tid - 48);                 d = bdst + 768 + (tid - 48) * 16; }
        else                { src = (const float4*)(g_e + (size_t)n * V_PTS + v0) + (tid - 112); d = bdst + 1792 + (tid - 112) * 16; }
        CP16(d, src);
    }

    const float* base = lc + ((size_t)n * V_PTS + v0) * XYZ;   // contiguous 32256 B tile
    uintptr_t ba = (uintptr_t)base & ~(uintptr_t)15;
    int off = (int)(((uintptr_t)base >> 2) & 3);
    int nch = 2016 + (off ? 1 : 0);
    uint32_t ldst = s2u(smc + FB_LCRAW);
    for (int i = tid; i < nch; i += 512)
        CP16(ldst + i * 16, (const void*)(ba + (uintptr_t)i * 16));
}

// =====================================================================
// Kernel A: encoder + decoder + effective L1 bias (fp32 exact)
// =====================================================================
__global__ void setup_kernel(
    const float* __restrict__ poses, const float* __restrict__ t_ped,
    const float* __restrict__ w,
    const float* __restrict__ Wec1, const float* __restrict__ bec1,
    const float* __restrict__ Wec21, const float* __restrict__ bec21,
    const float* __restrict__ Wec22, const float* __restrict__ bec22,
    const float* __restrict__ Wdc1, const float* __restrict__ bdc1,
    const float* __restrict__ Wdc21, const float* __restrict__ bdc21,
    const float* __restrict__ Wdc22, const float* __restrict__ bdc22,
    const float* __restrict__ Wf1, const float* __restrict__ bf1,
    float* __restrict__ out)
{
    int n = blockIdx.x;
    int t = threadIdx.x;
    __shared__ float s_in[88], s_net[64], s_mean[8], s_din[80], s_net2[64], s_ei[32];

    if (t < 72)       s_in[t] = w[n * 24 + t / 3] * poses[n * 72 + t];
    else if (t < 88)  s_in[t] = t_ped[t - 72];
    __syncthreads();

    if (t < 64) {
        float a = bec1[n * 64 + t];
        const float* Wr = &Wec1[(n * 64 + t) * 88];
        #pragma unroll 8
        for (int c = 0; c < 88; c++) a += Wr[c] * s_in[c];
        s_net[t] = fmaxf(a, 0.f);
    }
    __syncthreads();

    if (t < 8) {
        float m = bec21[n * 8 + t], lv = bec22[n * 8 + t];
        const float* Wm = &Wec21[(n * 8 + t) * 64];
        const float* Wl = &Wec22[(n * 8 + t) * 64];
        #pragma unroll 8
        for (int c = 0; c < 64; c++) { m += Wm[c] * s_net[c]; lv += Wl[c] * s_net[c]; }
        s_mean[t] = m;
        out[OFF_MEAN + n * 8 + t] = m;
        out[OFF_LOGVAR + n * 8 + t] = lv;
    }
    __syncthreads();

    if (t < 72)      s_din[t] = s_in[t];
    else if (t < 80) s_din[t] = s_mean[t - 72];
    __syncthreads();

    if (t < 64) {
        float a = bdc1[n * 64 + t];
        const float* Wr = &Wdc1[(n * 64 + t) * 80];
        #pragma unroll 8
        for (int c = 0; c < 80; c++) a += Wr[c] * s_din[c];
        s_net2[t] = fmaxf(a, 0.f);
    }
    __syncthreads();

    if (t < 32) {
        float a = bdc21[n * 32 + t];
        const float* Wr = &Wdc21[(n * 32 + t) * 64];
        #pragma unroll 8
        for (int c = 0; c < 64; c++) a += Wr[c] * s_net2[c];
        s_ei[t] = a;
        g_ei[n * 32 + t] = a;
        out[OFF_EI + n * 32 + t] = a;
    }
    if (t >= 32 && t < 35) {
        int j = t - 32;
        float a = bdc22[n * 3 + j];
        const float* Wr = &Wdc22[(n * 3 + j) * 64];
        #pragma unroll 8
        for (int c = 0; c < 64; c++) a += Wr[c] * s_net2[c];
        out[OFF_DELTA + n * 3 + j] = a;
    }
    __syncthreads();

    if (t < 64) {
        float a = bf1[n * 64 + t];
        const float* Wr = &Wf1[(size_t)(n * 64 + t) * 95];
        #pragma unroll 8
        for (int c = 0; c < 32; c++) a += Wr[c] * s_ei[c];
        g_b1eff[n * 64 + t] = a;
    }
}

// =====================================================================
// Kernel E+B merged: blocks 0..127 prepack weights -> f16 images,
//                    blocks 128..135 compute RBF blend weights.
// =====================================================================
__global__ void prep_kernel(const float* __restrict__ Wf1,
                            const float* __restrict__ Wf2,
                            const float* __restrict__ Wf3,
                            const float* __restrict__ Wf4,
                            const float* __restrict__ wpts,
                            const float* __restrict__ nodes_posed)
{
    int bid = blockIdx.x, tid = threadIdx.x;
    if (bid < N_NODES) {
        int n = bid;
        __half* dst = (__half*)&g_Wpad4[(size_t)n * 4032];

        for (int i = tid; i < 4608; i += 256) {            // W1 [64 x 72]
            int j = i / 72, k = i - j * 72;
            float v = (k < XYZ) ? Wf1[(size_t)(n * 64 + j) * 95 + 32 + k] : 0.f;
            dst[i] = __float2half_rn(v);
        }
        for (int i = tid; i < 4608; i += 256) {            // W2
            int j = i / 72, k = i - j * 72;
            float v = (k < 64) ? Wf2[(size_t)n * 4096 + j * 64 + k] : 0.f;
            dst[4608 + i] = __float2half_rn(v);
        }
        for (int i = tid; i < 4608; i += 256) {            // W3
            int j = i / 72, k = i - j * 72;
            float v = (k < 64) ? Wf3[(size_t)n * 4096 + j * 64 + k] : 0.f;
            dst[9216 + i] = __float2half_rn(v);
        }
        for (int i = tid; i < 18432; i += 256) {           // W4 [256 x 72]
            int j = i / 72, k = i - j * 72;
            float v = (k < 64) ? Wf4[(size_t)n * 16384 + j * 64 + k] : 0.f;
            dst[13824 + i] = __float2half_rn(v);
        }
    } else {
        int v = (bid - N_NODES) * 256 + tid;
        if (v >= V_PTS) return;
        float px = wpts[v * 3 + 0], py = wpts[v * 3 + 1], pz = wpts[v * 3 + 2];
        float denom = 0.f;
        for (int n = 0; n < N_NODES; n++) {
            float dx = px - nodes_posed[n * 3 + 0];
            float dy = py - nodes_posed[n * 3 + 1];
            float dz = pz - nodes_posed[n * 3 + 2];
            float d2 = dx * dx + dy * dy + dz * dz;
            float influ = expf(-d2 * (1.0f / 0.18f)) - 0.01f;
            float e = (influ >= 0.f) ? (influ + 1e-7f) : 0.f;
            denom += fmaxf(influ, 0.f) + 1e-7f;
            g_e[n * V_PTS + v] = e;
        }
        float inv = 1.0f / denom;
        for (int n = 0; n < N_NODES; n++) g_e[n * V_PTS + v] *= inv;
    }
}

// =====================================================================
// Kernel C: feature field via mma.sync f16 + cp.async double-buffering
// grid = (16 v-tiles) x (9 node-groups), 512 threads (16 warps)
// =====================================================================
__global__ void __launch_bounds__(512, 1) field_kernel(
    const float* __restrict__ local_coords,
    const float* __restrict__ bf2, const float* __restrict__ bf3,
    const float* __restrict__ bf4)
{
    extern __shared__ char smc[];
    __half*   smh = (__half*)smc;
    uint32_t* smw = (uint32_t*)smc;
    float*    smf = (float*)smc;

    int tid  = threadIdx.x;
    int wid  = tid >> 5, lane = tid & 31;
    int mb   = wid & 7;
    int nhi  = wid >> 3;
    int v0 = blockIdx.x * 128;
    int g  = blockIdx.y;
    int n0 = g * 15;
    int ncnt = (g == 8) ? 8 : 15;
    int cb = nhi * 32;

    float acc[64];
    #pragma unroll
    for (int i = 0; i < 64; i++) acc[i] = 0.f;

    int r0 = mb * 16 + (lane >> 2);
    int q2 = (lane & 3) * 2;

    // prologue: prefetch first node
    prefetch_node(smc, 0, n0, v0, tid, bf2, bf3, bf4, local_coords);
    CP_COMMIT();
    int cur = 0;

    for (int ni = 0; ni < ncnt; ni++) {
        int n = n0 + ni;
        CP_WAIT0();
        __syncthreads();   // weights[cur]/biases/lcraw complete; prev node reads done

        // ---- convert lcraw (fp32) -> BUFA (f16) ----
        {
            const float* base = local_coords + ((size_t)n * V_PTS + v0) * XYZ;
            int off = (int)(((uintptr_t)base >> 2) & 3);
            const float* lcr = (const float*)(smc + FB_LCRAW);
            #pragma unroll 4
            for (int i = tid; i < 8192; i += 512) {
                int v = i >> 6, k = i & 63;
                float val = (k < XYZ) ? lcr[off + v * 63 + k] : 0.f;
                smh[FB_BUFA / 2 + v * 72 + k] = __float2half_rn(val);
            }
        }
        __syncthreads();   // BUFA ready; lcraw free for next prefetch

        // ---- kick prefetch of next node into the other buffer ----
        if (ni + 1 < ncnt)
            prefetch_node(smc, cur ^ 1, n + 1, v0, tid, bf2, bf3, bf4, local_coords);
        CP_COMMIT();

        const uint32_t* Wbase = smw + FB_W(cur) / 4;
        int bsf = FB_BS(cur) / 4;          // f32 index of bias block
        float ev0 = smf[bsf + 448 + r0];
        float ev1 = smf[bsf + 448 + r0 + 8];

        const uint32_t* wA = smw + FB_BUFA / 4;
        const uint32_t* wB = smw + FB_BUFB / 4;

        // ================= L1: bufA -> bufB =================
        {
            float c[4][4];
            #pragma unroll
            for (int a = 0; a < 4; a++)
                #pragma unroll
                for (int b = 0; b < 4; b++) c[a][b] = 0.f;
            gemm16x32_f16(wA, Wbase, mb, cb, lane, c);
            #pragma unroll
            for (int n8 = 0; n8 < 4; n8++) {
                int cc = cb + n8 * 8 + q2;
                float b0 = smf[bsf + cc], b1 = smf[bsf + cc + 1];
                ((__half2*)smc)[FB_BUFB / 4 + r0 * 36 + (cc >> 1)] =
                    __floats2half2_rn(fmaxf(c[n8][0] + b0, 0.f), fmaxf(c[n8][1] + b1, 0.f));
                ((__half2*)smc)[FB_BUFB / 4 + (r0 + 8) * 36 + (cc >> 1)] =
                    __floats2half2_rn(fmaxf(c[n8][2] + b0, 0.f), fmaxf(c[n8][3] + b1, 0.f));
            }
        }
        __syncthreads();

        // ================= L2: bufB -> bufA =================
        {
            float c[4][4];
            #pragma unroll
            for (int a = 0; a < 4; a++)
                #pragma unroll
                for (int b = 0; b < 4; b++) c[a][b] = 0.f;
            gemm16x32_f16(wB, Wbase + 4608 / 2, mb, cb, lane, c);   // +9216B
            #pragma unroll
            for (int n8 = 0; n8 < 4; n8++) {
                int cc = cb + n8 * 8 + q2;
                float b0 = smf[bsf + 64 + cc], b1 = smf[bsf + 64 + cc + 1];
                ((__half2*)smc)[FB_BUFA / 4 + r0 * 36 + (cc >> 1)] =
                    __floats2half2_rn(fmaxf(c[n8][0] + b0, 0.f), fmaxf(c[n8][1] + b1, 0.f));
                ((__half2*)smc)[FB_BUFA / 4 + (r0 + 8) * 36 + (cc >> 1)] =
                    __floats2half2_rn(fmaxf(c[n8][2] + b0, 0.f), fmaxf(c[n8][3] + b1, 0.f));
            }
        }
        __syncthreads();

        // ================= L3: bufA -> bufB =================
        {
            float c[4][4];
            #pragma unroll
            for (int a = 0; a < 4; a++)
                #pragma unroll
                for (int b = 0; b < 4; b++) c[a][b] = 0.f;
            gemm16x32_f16(wA, Wbase + 9216 / 2, mb, cb, lane, c);   // +18432B
            #pragma unroll
            for (int n8 = 0; n8 < 4; n8++) {
                int cc = cb + n8 * 8 + q2;
                float b0 = smf[bsf + 128 + cc], b1 = smf[bsf + 128 + cc + 1];
                ((__half2*)smc)[FB_BUFB / 4 + r0 * 36 + (cc >> 1)] =
                    __floats2half2_rn(fmaxf(c[n8][0] + b0, 0.f), fmaxf(c[n8][1] + b1, 0.f));
                ((__half2*)smc)[FB_BUFB / 4 + (r0 + 8) * 36 + (cc >> 1)] =
                    __floats2half2_rn(fmaxf(c[n8][2] + b0, 0.f), fmaxf(c[n8][3] + b1, 0.f));
            }
        }
        __syncthreads();

        // ================= L4: bufB x W4 (256 cols, 4 rounds) =================
        #pragma unroll
        for (int rnd = 0; rnd < 4; rnd++) {
            float c[4][4];
            #pragma unroll
            for (int a = 0; a < 4; a++)
                #pragma unroll
                for (int b = 0; b < 4; b++) c[a][b] = 0.f;
            int cb4 = rnd * 64 + cb;
            gemm16x32_f16(wB, Wbase + 13824 / 2, mb, cb4, lane, c); // +27648B
            #pragma unroll
            for (int n8 = 0; n8 < 4; n8++) {
                int cc = cb4 + n8 * 8 + q2;
                float b0 = smf[bsf + 192 + cc], b1 = smf[bsf + 192 + cc + 1];
                int ai = rnd * 16 + n8 * 4;
                acc[ai + 0] += ev0 * fmaxf(c[n8][0] + b0, 0.f);
                acc[ai + 1] += ev0 * fmaxf(c[n8][1] + b1, 0.f);
                acc[ai + 2] += ev1 * fmaxf(c[n8][2] + b0, 0.f);
                acc[ai + 3] += ev1 * fmaxf(c[n8][3] + b1, 0.f);
            }
        }
        cur ^= 1;
        // loop-top __syncthreads() covers L4-read completion before restage
    }

    // ---- write this group's partial tile ----
    {
        size_t base0 = ((size_t)g * V_PTS + v0 + r0) * 256;
        size_t base1 = ((size_t)g * V_PTS + v0 + r0 + 8) * 256;
        #pragma unroll
        for (int rnd = 0; rnd < 4; rnd++) {
            #pragma unroll
            for (int n8 = 0; n8 < 4; n8++) {
                int cc = rnd * 64 + cb + n8 * 8 + q2;
                int ai = rnd * 16 + n8 * 4;
                *(float2*)&g_fpart[base0 + cc] = make_float2(acc[ai + 0], acc[ai + 1]);
                *(float2*)&g_fpart[base1 + cc] = make_float2(acc[ai + 2], acc[ai + 3]);
            }
        }
    }
}

// =====================================================================
// Kernel D: reduce partials + NeRF head. 4 points per block, 256 thr.
// =====================================================================
__global__ void head_kernel(const float* __restrict__ Wc1, const float* __restrict__ bc1,
                            const float* __restrict__ Wc2, const float* __restrict__ bc2,
                            const float* __restrict__ Wd1, const float* __restrict__ bd1,
                            float* __restrict__ out)
{
    int sub = threadIdx.x >> 6;
    int t   = threadIdx.x & 63;
    int v   = blockIdx.x * 4 + sub;
    __shared__ float f_s[4][256];
    __shared__ float netc_s[4][64];

    {
        float4 s = make_float4(0.f, 0.f, 0.f, 0.f);
        #pragma unroll
        for (int g2 = 0; g2 < NG; g2++) {
            float4 p = *(const float4*)&g_fpart[((size_t)g2 * V_PTS + v) * 256 + t * 4];
            s.x += p.x; s.y += p.y; s.z += p.z; s.w += p.w;
        }
        *(float4*)&f_s[sub][t * 4] = s;
    }
    __syncthreads();

    {
        float a0 = 0.f, a1 = 0.f, a2 = 0.f, a3 = 0.f;
        #pragma unroll 8
        for (int c = 0; c < 256; c += 4) {
            a0 += f_s[sub][c + 0] * Wc1[(c + 0) * 64 + t];
            a1 += f_s[sub][c + 1] * Wc1[(c + 1) * 64 + t];
            a2 += f_s[sub][c + 2] * Wc1[(c + 2) * 64 + t];
            a3 += f_s[sub][c + 3] * Wc1[(c + 3) * 64 + t];
        }
        netc_s[sub][t] = fmaxf(bc1[t] + ((a0 + a1) + (a2 + a3)), 0.f);
    }
    __syncthreads();

    if (t < 3) {
        float r = bc2[t];
        #pragma unroll 8
        for (int j = 0; j < 64; j++) r += netc_s[sub][j] * Wc2[j * 3 + t];
        out[OFF_C + v * 3 + t] = r;
    } else if (t == 3) {
        float r0 = 0.f, r1 = 0.f, r2 = 0.f, r3 = 0.f;
        #pragma unroll 8
        for (int c = 0; c < 256; c += 4) {
            r0 += f_s[sub][c + 0] * Wd1[c + 0];
            r1 += f_s[sub][c + 1] * Wd1[c + 1];
            r2 += f_s[sub][c + 2] * Wd1[c + 2];
            r3 += f_s[sub][c + 3] * Wd1[c + 3];
        }
        out[OFF_D + v] = fmaxf(bd1[0] + ((r0 + r1) + (r2 + r3)), 0.f);
    }
}

// =====================================================================
extern "C" void kernel_launch(void* const* d_in, const int* in_sizes, int n_in,
                              void* d_out, int out_size)
{
    const float* poses = (const float*)d_in[0];
    const float* t_ped = (const float*)d_in[1];
    const float* w     = (const float*)d_in[2];
    const float* wpts  = (const float*)d_in[3];
    const float* nodes = (const float*)d_in[4];
    const float* lc    = (const float*)d_in[5];
    const float *Wec1 = (const float*)d_in[6],  *bec1 = (const float*)d_in[7];
    const float *Wec21= (const float*)d_in[8],  *bec21= (const float*)d_in[9];
    const float *Wec22= (const float*)d_in[10], *bec22= (const float*)d_in[11];
    const float *Wdc1 = (const float*)d_in[12], *bdc1 = (const float*)d_in[13];
    const float *Wdc21= (const float*)d_in[14], *bdc21= (const float*)d_in[15];
    const float *Wdc22= (const float*)d_in[16], *bdc22= (const float*)d_in[17];
    const float *Wf1  = (const float*)d_in[18], *bf1  = (const float*)d_in[19];
    const float *Wf2  = (const float*)d_in[20], *bf2  = (const float*)d_in[21];
    const float *Wf3  = (const float*)d_in[22], *bf3  = (const float*)d_in[23];
    const float *Wf4  = (const float*)d_in[24], *bf4  = (const float*)d_in[25];
    const float *Wc1  = (const float*)d_in[26], *bc1  = (const float*)d_in[27];
    const float *Wc2  = (const float*)d_in[28], *bc2  = (const float*)d_in[29];
    const float *Wd1  = (const float*)d_in[30], *bd1  = (const float*)d_in[31];
    float* out = (float*)d_out;

    setup_kernel<<<N_NODES, 128>>>(poses, t_ped, w,
                                   Wec1, bec1, Wec21, bec21, Wec22, bec22,
                                   Wdc1, bdc1, Wdc21, bdc21, Wdc22, bdc22,
                                   Wf1, bf1, out);
    prep_kernel<<<N_NODES + V_PTS / 256, 256>>>(Wf1, Wf2, Wf3, Wf4, wpts, nodes);

    cudaFuncSetAttribute(field_kernel,
                         cudaFuncAttributeMaxDynamicSharedMemorySize, FB_TOT);
    field_kernel<<<dim3(V_PTS / 128, NG), 512, FB_TOT>>>(lc, bf2, bf3, bf4);

    head_kernel<<<V_PTS / 4, 256>>>(Wc1, bc1, Wc2, bc2, Wd1, bd1, out);
}